// round 2
// baseline (speedup 1.0000x reference)
#include <cuda_runtime.h>
#include <cuda_fp16.h>
#include <math.h>

#define NN 100000
#define EE 1600000
#define DIN 128
#define DH  256
#define PADR 136

// ---- device scratch (allocation-free contract: __device__ globals) ----
__device__ float  g_agg[2ull * NN * DIN];     // fp32 agg (102.4 MB)
__device__ __half g_h16[2ull * NN * DH];      // fp16 h  (102.4 MB)
__device__ uint4  g_xh[(size_t)NN * 32];      // interleaved fp16 x|x_tilde: [N][256] halves (51.2 MB)
__device__ float  g_colsum[DH];
__device__ float  g_v[DH];
__device__ float  g_W1t[DIN * DH];            // W1 transposed: [k][j]
__device__ int    g_rowptr[NN + 1];

// ------------------------------------------------------------------
__global__ void k_init() {
    int t = threadIdx.x;
    if (t < DH) g_colsum[t] = 0.0f;
}

// W1 [DH][DIN] -> W1t [DIN][DH]
__global__ void k_transpose(const float* __restrict__ W1) {
    int idx = blockIdx.x * blockDim.x + threadIdx.x;
    if (idx < DIN * DH) {
        int k = idx / DH, j = idx % DH;
        g_W1t[idx] = W1[j * DIN + k];
    }
}

// rowptr from sorted adj_row
__global__ void k_rowptr(const int* __restrict__ adj_row) {
    int e = blockIdx.x * blockDim.x + threadIdx.x;
    if (e >= EE) return;
    int r  = adj_row[e];
    int rp = (e == 0) ? -1 : adj_row[e - 1];
    for (int k = rp + 1; k <= r; k++) g_rowptr[k] = e;
    if (e == EE - 1) {
        for (int k = r + 1; k <= NN; k++) g_rowptr[k] = EE;
    }
}

// ------------------------------------------------------------------
// Convert x and x_tilde to fp16, interleaved per node: row = [x(128h) | xt(128h)] = 512B
__global__ void k_cvt(const float4* __restrict__ x4, const float4* __restrict__ xt4) {
    int i = blockIdx.x * blockDim.x + threadIdx.x;
    if (i >= NN * 32) return;
    int row = i >> 5, j = i & 31;
    const float4* src = (j < 16) ? x4 : xt4;
    int jj = j & 15;
    float4 a = src[(size_t)row * 32 + jj * 2];
    float4 b = src[(size_t)row * 32 + jj * 2 + 1];
    __half2 h0 = __floats2half2_rn(a.x, a.y);
    __half2 h1 = __floats2half2_rn(a.z, a.w);
    __half2 h2 = __floats2half2_rn(b.x, b.y);
    __half2 h3 = __floats2half2_rn(b.z, b.w);
    uint4 o;
    o.x = *(unsigned*)&h0; o.y = *(unsigned*)&h1;
    o.z = *(unsigned*)&h2; o.w = *(unsigned*)&h3;
    g_xh[(size_t)row * 32 + j] = o;
}

// ------------------------------------------------------------------
// SpMM: one warp per row. Each edge gathers ONE 512B line (fp16 x|xt interleaved).
// Lanes 0-15 accumulate x features (8 each), lanes 16-31 accumulate x_tilde.
__global__ void k_spmm(const float* __restrict__ vals, const int* __restrict__ cols) {
    int w    = (blockIdx.x * blockDim.x + threadIdx.x) >> 5;
    int lane = threadIdx.x & 31;
    if (w >= NN) return;
    int e0 = g_rowptr[w], e1 = g_rowptr[w + 1];
    float a0 = 0.f, a1 = 0.f, a2 = 0.f, a3 = 0.f, a4 = 0.f, a5 = 0.f, a6 = 0.f, a7 = 0.f;
#pragma unroll 4
    for (int e = e0; e < e1; e++) {
        float wt = __ldg(vals + e);
        int   c  = __ldg(cols + e);
        uint4 u  = g_xh[(size_t)c * 32 + lane];
        float2 f0 = __half22float2(*(const __half2*)&u.x);
        float2 f1 = __half22float2(*(const __half2*)&u.y);
        float2 f2 = __half22float2(*(const __half2*)&u.z);
        float2 f3 = __half22float2(*(const __half2*)&u.w);
        a0 += wt * f0.x; a1 += wt * f0.y;
        a2 += wt * f1.x; a3 += wt * f1.y;
        a4 += wt * f2.x; a5 += wt * f2.y;
        a6 += wt * f3.x; a7 += wt * f3.y;
    }
    size_t base = (lane < 16) ? (size_t)w : (size_t)NN + w;
    int j = lane & 15;
    float4* out = (float4*)g_agg;
    out[base * 32 + j * 2]     = make_float4(a0, a1, a2, a3);
    out[base * 32 + j * 2 + 1] = make_float4(a4, a5, a6, a7);
}

// ------------------------------------------------------------------
// GEMM: h = PReLU(agg @ W1^T), fused column-sum (rows < NN), h stored fp16.
// A tile stored TRANSPOSED in smem (As[k][row], PADR pad) -> conflict-free LDS.128.
__global__ void __launch_bounds__(256, 1) k_gemm(const float* __restrict__ prelu_a) {
    extern __shared__ float smem[];
    float* As = smem;                 // [128][PADR]  (transposed: As[k*PADR + row])
    float* Bs = smem + 128 * PADR;    // [128][DH]
    int tid = threadIdx.x;
    int tx = tid & 15, ty = tid >> 4;
    long rowBase = (long)blockIdx.x * 128;
    const long totalRows = 2L * NN;

    // Load Bs (coalesced copy of W1t)
    {
        const float4* src = (const float4*)g_W1t;
        float4* dst = (float4*)Bs;
#pragma unroll
        for (int i = 0; i < 32; i++) dst[tid + i * 256] = src[tid + i * 256];
    }
    // Load As transposed: read row-major float4, scatter as columns
    {
        const float4* src = (const float4*)g_agg;
#pragma unroll
        for (int i = 0; i < 16; i++) {
            int idx = tid + i * 256;          // 4096 float4 covers 128 rows x 32
            int row = idx >> 5, k4 = idx & 31;
            long grow = rowBase + row;
            float4 v = make_float4(0.f, 0.f, 0.f, 0.f);
            if (grow < totalRows) v = src[grow * 32 + k4];
            int kb = k4 * 4;
            As[(kb + 0) * PADR + row] = v.x;
            As[(kb + 1) * PADR + row] = v.y;
            As[(kb + 2) * PADR + row] = v.z;
            As[(kb + 3) * PADR + row] = v.w;
        }
    }
    __syncthreads();

    float pa = prelu_a[0];
    float csum[16];
#pragma unroll
    for (int i = 0; i < 16; i++) csum[i] = 0.f;

#pragma unroll
    for (int gpass = 0; gpass < 2; gpass++) {
        unsigned long long acc[8][4];
#pragma unroll
        for (int m = 0; m < 8; m++)
#pragma unroll
            for (int p = 0; p < 4; p++) acc[m][p] = 0ull;
        int jbase0 = tx * 4 + (gpass * 2 + 0) * 64;
        int jbase1 = tx * 4 + (gpass * 2 + 1) * 64;
#pragma unroll 4
        for (int k = 0; k < DIN; k++) {
            const float* ak = As + k * PADR + ty * 8;
            float4 av0 = *(const float4*)ak;
            float4 av1 = *(const float4*)(ak + 4);
            unsigned long long ap[8];
            asm("mov.b64 %0, {%1, %1};" : "=l"(ap[0]) : "f"(av0.x));
            asm("mov.b64 %0, {%1, %1};" : "=l"(ap[1]) : "f"(av0.y));
            asm("mov.b64 %0, {%1, %1};" : "=l"(ap[2]) : "f"(av0.z));
            asm("mov.b64 %0, {%1, %1};" : "=l"(ap[3]) : "f"(av0.w));
            asm("mov.b64 %0, {%1, %1};" : "=l"(ap[4]) : "f"(av1.x));
            asm("mov.b64 %0, {%1, %1};" : "=l"(ap[5]) : "f"(av1.y));
            asm("mov.b64 %0, {%1, %1};" : "=l"(ap[6]) : "f"(av1.z));
            asm("mov.b64 %0, {%1, %1};" : "=l"(ap[7]) : "f"(av1.w));
            ulonglong2 b0 = *(const ulonglong2*)(Bs + k * DH + jbase0);
            ulonglong2 b1 = *(const ulonglong2*)(Bs + k * DH + jbase1);
#pragma unroll
            for (int m = 0; m < 8; m++) {
                asm("fma.rn.f32x2 %0, %1, %2, %0;" : "+l"(acc[m][0]) : "l"(ap[m]), "l"(b0.x));
                asm("fma.rn.f32x2 %0, %1, %2, %0;" : "+l"(acc[m][1]) : "l"(ap[m]), "l"(b0.y));
                asm("fma.rn.f32x2 %0, %1, %2, %0;" : "+l"(acc[m][2]) : "l"(ap[m]), "l"(b1.x));
                asm("fma.rn.f32x2 %0, %1, %2, %0;" : "+l"(acc[m][3]) : "l"(ap[m]), "l"(b1.y));
            }
        }
        // Epilogue: unpack, PReLU, store h (fp16), accumulate column partial sums
#pragma unroll
        for (int m = 0; m < 8; m++) {
            long row = rowBase + ty * 8 + m;
            if (row < totalRows) {
                float z[8];
#pragma unroll
                for (int p = 0; p < 4; p++) {
                    float lo, hi;
                    asm("mov.b64 {%0, %1}, %2;" : "=f"(lo), "=f"(hi) : "l"(acc[m][p]));
                    z[p * 2] = lo; z[p * 2 + 1] = hi;
                }
#pragma unroll
                for (int q = 0; q < 8; q++) z[q] = (z[q] >= 0.f) ? z[q] : pa * z[q];
                __half2 h0 = __floats2half2_rn(z[0], z[1]);
                __half2 h1 = __floats2half2_rn(z[2], z[3]);
                __half2 h2 = __floats2half2_rn(z[4], z[5]);
                __half2 h3 = __floats2half2_rn(z[6], z[7]);
                uint2 u0, u1;
                u0.x = *(unsigned*)&h0; u0.y = *(unsigned*)&h1;
                u1.x = *(unsigned*)&h2; u1.y = *(unsigned*)&h3;
                *(uint2*)(g_h16 + (size_t)row * DH + jbase0) = u0;
                *(uint2*)(g_h16 + (size_t)row * DH + jbase1) = u1;
                if (row < NN) {
#pragma unroll
                    for (int q = 0; q < 8; q++) csum[gpass * 8 + q] += z[q];
                }
            }
        }
    }

    // Column-sum reduction: red[j][ty] in smem, then 256 global atomics.
    __syncthreads();
    float* red = smem;  // DH*16 floats = 16 KB
#pragma unroll
    for (int s = 0; s < 16; s++) {
        int gp = s >> 3, q = s & 7;
        int j = tx * 4 + (gp * 2 + (q >> 2)) * 64 + (q & 3);
        red[j * 16 + ty] = csum[s];
    }
    __syncthreads();
    if (tid < DH) {
        float t = 0.f;
#pragma unroll
        for (int u = 0; u < 16; u++) t += red[tid * 16 + u];
        atomicAdd(&g_colsum[tid], t);
    }
}

// ------------------------------------------------------------------
// s = sigmoid(colsum/N); v = w_bil @ s
__global__ void k_sv(const float* __restrict__ w_bil) {
    __shared__ float s[DH];
    int t = threadIdx.x;
    float m = g_colsum[t] / (float)NN;
    s[t] = 1.f / (1.f + expf(-m));
    __syncthreads();
    float acc = 0.f;
#pragma unroll 8
    for (int j = 0; j < DH; j++) acc += w_bil[t * DH + j] * s[j];
    g_v[t] = acc;
}

// ------------------------------------------------------------------
// out[row] = dot(h[row], v), h in fp16 (one uint4 = 8 halves per lane).
__global__ void k_dot(float* __restrict__ out) {
    __shared__ float vs[DH];
    if (threadIdx.x < DH) vs[threadIdx.x] = g_v[threadIdx.x];
    __syncthreads();
    int w    = (blockIdx.x * blockDim.x + threadIdx.x) >> 5;
    int lane = threadIdx.x & 31;
    if (w >= 2 * NN) return;
    uint4 u = *(const uint4*)(g_h16 + (size_t)w * DH + lane * 8);
    float4 v0 = ((const float4*)vs)[lane * 2];
    float4 v1 = ((const float4*)vs)[lane * 2 + 1];
    float2 f0 = __half22float2(*(const __half2*)&u.x);
    float2 f1 = __half22float2(*(const __half2*)&u.y);
    float2 f2 = __half22float2(*(const __half2*)&u.z);
    float2 f3 = __half22float2(*(const __half2*)&u.w);
    float acc = f0.x * v0.x + f0.y * v0.y + f1.x * v0.z + f1.y * v0.w
              + f2.x * v1.x + f2.y * v1.y + f3.x * v1.z + f3.y * v1.w;
#pragma unroll
    for (int o = 16; o > 0; o >>= 1) acc += __shfl_xor_sync(0xffffffffu, acc, o);
    if (lane == 0) out[w] = acc;
}

// ------------------------------------------------------------------
extern "C" void kernel_launch(void* const* d_in, const int* in_sizes, int n_in,
                              void* d_out, int out_size) {
    const float* x       = (const float*)d_in[0];
    const float* x_tilde = (const float*)d_in[1];
    const float* vals    = (const float*)d_in[2];
    const int*   adj_row = (const int*)d_in[3];
    const int*   adj_col = (const int*)d_in[4];
    const float* W1      = (const float*)d_in[5];
    const float* prelu_a = (const float*)d_in[6];
    const float* w_bil   = (const float*)d_in[7];
    float* out = (float*)d_out;

    cudaFuncSetAttribute(k_gemm, cudaFuncAttributeMaxDynamicSharedMemorySize,
                         128 * PADR * 4 + 128 * DH * 4);

    k_init<<<1, 256>>>();
    k_transpose<<<(DIN * DH + 255) / 256, 256>>>(W1);
    k_rowptr<<<(EE + 255) / 256, 256>>>(adj_row);
    k_cvt<<<(NN * 32 + 255) / 256, 256>>>((const float4*)x, (const float4*)x_tilde);
    k_spmm<<<(NN * 32) / 256, 256>>>(vals, adj_col);
    k_gemm<<<(2 * NN + 127) / 128, 256, 128 * PADR * 4 + 128 * DH * 4>>>(prelu_a);
    k_sv<<<1, DH>>>(w_bil);
    k_dot<<<(2 * NN * 32 + 255) / 256, 256>>>(out);
}

// round 4
// speedup vs baseline: 2.0698x; 2.0698x over previous
#include <cuda_runtime.h>
#include <cuda_fp16.h>
#include <math.h>
#include <stdint.h>

#define NN 100000
#define EE 1600000
#define DIN 128
#define DH  256

// ---- device scratch (allocation-free contract) ----
__device__ uint4  g_xh[(size_t)NN * 32];        // interleaved fp16 x|x_tilde [N][256]h (51.2MB)
__device__ __half g_agg16[2ull * NN * DIN];     // fp16 agg (51.2MB)
__device__ __half g_h16[2ull * NN * DH];        // fp16 h   (102.4MB)
__device__ __half g_W1h[DH * DIN];              // fp16 W1, native [N=256][K=128] K-major
__device__ float  g_colsum[DH];
__device__ float  g_v[DH];
__device__ int    g_rowptr[NN + 1];

// ================= helpers =================
__device__ __forceinline__ uint32_t smem_u32(const void* p) {
    uint32_t a;
    asm("{ .reg .u64 t; cvta.to.shared.u64 t, %1; cvt.u32.u64 %0, t; }" : "=r"(a) : "l"(p));
    return a;
}
__device__ __forceinline__ void ldsm_x4(uint32_t& r0, uint32_t& r1, uint32_t& r2, uint32_t& r3,
                                        uint32_t addr) {
    asm volatile("ldmatrix.sync.aligned.m8n8.x4.shared.b16 {%0,%1,%2,%3}, [%4];"
                 : "=r"(r0), "=r"(r1), "=r"(r2), "=r"(r3) : "r"(addr));
}
__device__ __forceinline__ void mma16816(float* d, const uint32_t* a, const uint32_t* b) {
    asm volatile("mma.sync.aligned.m16n8k16.row.col.f32.f16.f16.f32 "
                 "{%0,%1,%2,%3}, {%4,%5,%6,%7}, {%8,%9}, {%0,%1,%2,%3};"
                 : "+f"(d[0]), "+f"(d[1]), "+f"(d[2]), "+f"(d[3])
                 : "r"(a[0]), "r"(a[1]), "r"(a[2]), "r"(a[3]), "r"(b[0]), "r"(b[1]));
}

// ================= prep kernels =================
__global__ void k_init() {
    int t = threadIdx.x;
    if (t < DH) g_colsum[t] = 0.0f;
}

__global__ void k_cvtW(const float* __restrict__ W1) {
    int i = blockIdx.x * blockDim.x + threadIdx.x;
    if (i < DH * DIN) g_W1h[i] = __float2half_rn(W1[i]);
}

__global__ void k_rowptr(const int* __restrict__ adj_row) {
    int e = blockIdx.x * blockDim.x + threadIdx.x;
    if (e >= EE) return;
    int r  = adj_row[e];
    int rp = (e == 0) ? -1 : adj_row[e - 1];
    for (int k = rp + 1; k <= r; k++) g_rowptr[k] = e;
    if (e == EE - 1) {
        for (int k = r + 1; k <= NN; k++) g_rowptr[k] = EE;
    }
}

// x|x_tilde -> interleaved fp16 [N][256]h
__global__ void k_cvt(const float4* __restrict__ x4, const float4* __restrict__ xt4) {
    int i = blockIdx.x * blockDim.x + threadIdx.x;
    if (i >= NN * 32) return;
    int row = i >> 5, j = i & 31;
    const float4* src = (j < 16) ? x4 : xt4;
    int jj = j & 15;
    float4 a = src[(size_t)row * 32 + jj * 2];
    float4 b = src[(size_t)row * 32 + jj * 2 + 1];
    __half2 h0 = __floats2half2_rn(a.x, a.y);
    __half2 h1 = __floats2half2_rn(a.z, a.w);
    __half2 h2 = __floats2half2_rn(b.x, b.y);
    __half2 h3 = __floats2half2_rn(b.z, b.w);
    uint4 o;
    o.x = *(unsigned*)&h0; o.y = *(unsigned*)&h1;
    o.z = *(unsigned*)&h2; o.w = *(unsigned*)&h3;
    g_xh[(size_t)row * 32 + j] = o;
}

// ================= SpMM (fp16 gather, fp16 agg out) =================
__global__ void k_spmm(const float* __restrict__ vals, const int* __restrict__ cols) {
    int w    = (blockIdx.x * blockDim.x + threadIdx.x) >> 5;
    int lane = threadIdx.x & 31;
    if (w >= NN) return;
    int e0 = g_rowptr[w], e1 = g_rowptr[w + 1];
    float a0 = 0.f, a1 = 0.f, a2 = 0.f, a3 = 0.f, a4 = 0.f, a5 = 0.f, a6 = 0.f, a7 = 0.f;
#pragma unroll 4
    for (int e = e0; e < e1; e++) {
        float wt = __ldg(vals + e);
        int   c  = __ldg(cols + e);
        uint4 u  = g_xh[(size_t)c * 32 + lane];
        float2 f0 = __half22float2(*(const __half2*)&u.x);
        float2 f1 = __half22float2(*(const __half2*)&u.y);
        float2 f2 = __half22float2(*(const __half2*)&u.z);
        float2 f3 = __half22float2(*(const __half2*)&u.w);
        a0 += wt * f0.x; a1 += wt * f0.y;
        a2 += wt * f1.x; a3 += wt * f1.y;
        a4 += wt * f2.x; a5 += wt * f2.y;
        a6 += wt * f3.x; a7 += wt * f3.y;
    }
    size_t base = (lane < 16) ? (size_t)w : (size_t)NN + w;
    int j = lane & 15;
    __half2 h0 = __floats2half2_rn(a0, a1);
    __half2 h1 = __floats2half2_rn(a2, a3);
    __half2 h2 = __floats2half2_rn(a4, a5);
    __half2 h3 = __floats2half2_rn(a6, a7);
    uint4 o;
    o.x = *(unsigned*)&h0; o.y = *(unsigned*)&h1;
    o.z = *(unsigned*)&h2; o.w = *(unsigned*)&h3;
    ((uint4*)g_agg16)[base * 16 + j] = o;
}

// ================= HMMA GEMM =================
// h = PReLU(agg16[2N,128] @ W1h[256,128]^T), fused colsum for rows < NN.
// CTA tile 128x256, K=128 resident. 512 thr = 16 warps (2x8), warp tile 64x32.
#define LDA 136
#define LDB 136
#define LDS_STG 264
#define SM_BYTES (128 * LDA * 2 + 256 * LDB * 2)   // 104448

__global__ void __launch_bounds__(512, 1) k_gemm_mma(const float* __restrict__ prelu_a) {
    extern __shared__ __half smem[];
    __half* As = smem;               // [128][LDA]
    __half* Bs = smem + 128 * LDA;   // [256][LDB]
    int tid = threadIdx.x, lane = tid & 31, wid = tid >> 5;
    int warp_m = wid >> 3, warp_n = wid & 7;       // 2 x 8
    long rowBase = (long)blockIdx.x * 128;
    const long totalRows = 2L * NN;

    // ---- load A tile (zero-fill OOB rows) ----
    {
        const uint4* asrc = (const uint4*)g_agg16;
#pragma unroll
        for (int i = 0; i < 4; i++) {
            int c = tid + i * 512;
            int row = c >> 4, k4 = c & 15;
            long grow = rowBase + row;
            uint4 v = make_uint4(0u, 0u, 0u, 0u);
            if (grow < totalRows) v = asrc[(size_t)grow * 16 + k4];
            *(uint4*)(As + row * LDA + k4 * 8) = v;
        }
    }
    // ---- load B tile (all of W1h) ----
    {
        const uint4* bsrc = (const uint4*)g_W1h;
#pragma unroll
        for (int i = 0; i < 8; i++) {
            int c = tid + i * 512;
            int row = c >> 4, k4 = c & 15;
            *(uint4*)(Bs + row * LDB + k4 * 8) = bsrc[row * 16 + k4];
        }
    }
    __syncthreads();

    float acc[4][4][4];
#pragma unroll
    for (int mt = 0; mt < 4; mt++)
#pragma unroll
        for (int nt = 0; nt < 4; nt++)
#pragma unroll
            for (int q = 0; q < 4; q++) acc[mt][nt][q] = 0.f;

    // ldmatrix lane addressing
    int aRow = warp_m * 64 + (lane & 15);
    int aCol = (lane >> 4) * 8;
    int bGrp = lane >> 3;
    int bRowOff = ((bGrp >> 1) * 8) + (lane & 7);
    int bKadd = (bGrp & 1) * 8;

#pragma unroll
    for (int ks = 0; ks < 8; ks++) {
        uint32_t a[4][4];
#pragma unroll
        for (int mt = 0; mt < 4; mt++) {
            uint32_t addr = smem_u32(As + (aRow + mt * 16) * LDA + ks * 16 + aCol);
            ldsm_x4(a[mt][0], a[mt][1], a[mt][2], a[mt][3], addr);
        }
        uint32_t b[4][2];
#pragma unroll
        for (int np = 0; np < 2; np++) {
            uint32_t addr = smem_u32(Bs + (warp_n * 32 + np * 16 + bRowOff) * LDB + ks * 16 + bKadd);
            uint32_t r0, r1, r2, r3;
            ldsm_x4(r0, r1, r2, r3, addr);
            b[np * 2][0] = r0; b[np * 2][1] = r1;
            b[np * 2 + 1][0] = r2; b[np * 2 + 1][1] = r3;
        }
#pragma unroll
        for (int mt = 0; mt < 4; mt++)
#pragma unroll
            for (int nt = 0; nt < 4; nt++)
                mma16816(acc[mt][nt], a[mt], b[nt]);
    }
    __syncthreads();

    // ---- epilogue: PReLU -> fp16 -> smem stage ----
    float pa = prelu_a[0];
    __half* stg = smem;  // [128][LDS_STG]
    int r4 = lane >> 2, c4 = (lane & 3) * 2;
#pragma unroll
    for (int mt = 0; mt < 4; mt++) {
#pragma unroll
        for (int nt = 0; nt < 4; nt++) {
            float* d = acc[mt][nt];
            int row = warp_m * 64 + mt * 16 + r4;
            int col = warp_n * 32 + nt * 8 + c4;
            float z0 = (d[0] >= 0.f) ? d[0] : pa * d[0];
            float z1 = (d[1] >= 0.f) ? d[1] : pa * d[1];
            float z2 = (d[2] >= 0.f) ? d[2] : pa * d[2];
            float z3 = (d[3] >= 0.f) ? d[3] : pa * d[3];
            *(__half2*)(stg + row * LDS_STG + col)       = __floats2half2_rn(z0, z1);
            *(__half2*)(stg + (row + 8) * LDS_STG + col) = __floats2half2_rn(z2, z3);
        }
    }
    __syncthreads();

    // ---- coalesced writeout of h ----
#pragma unroll
    for (int i = 0; i < 8; i++) {
        int c = tid + i * 512;
        int row = c >> 5, q = c & 31;
        long grow = rowBase + row;
        if (grow < totalRows) {
            uint4 v = *(uint4*)(stg + row * LDS_STG + q * 8);
            *(uint4*)(g_h16 + (size_t)grow * 256 + q * 8) = v;
        }
    }
    // ---- fused column sum (rows < NN only) ----
    if (rowBase < NN) {
        int rmax = (NN - rowBase < 128) ? (int)(NN - rowBase) : 128;
        int cw = tid & 127, g = tid >> 7;        // 4 row-groups of 32
        int rlo = g * 32, rhi = (g + 1) * 32 < rmax ? (g + 1) * 32 : rmax;
        float s0 = 0.f, s1 = 0.f;
        for (int rr = rlo; rr < rhi; rr++) {
            __half2 hv = *(__half2*)(stg + rr * LDS_STG + cw * 2);
            float2 f = __half22float2(hv);
            s0 += f.x; s1 += f.y;
        }
        if (rlo < rhi) {
            atomicAdd(&g_colsum[2 * cw], s0);
            atomicAdd(&g_colsum[2 * cw + 1], s1);
        }
    }
}

// ================= readout / discriminator =================
__global__ void k_sv(const float* __restrict__ w_bil) {
    __shared__ float s[DH];
    int t = threadIdx.x;
    float m = g_colsum[t] / (float)NN;
    s[t] = 1.f / (1.f + expf(-m));
    __syncthreads();
    float acc = 0.f;
#pragma unroll 8
    for (int j = 0; j < DH; j++) acc += w_bil[t * DH + j] * s[j];
    g_v[t] = acc;
}

__global__ void k_dot(float* __restrict__ out) {
    __shared__ float vs[DH];
    if (threadIdx.x < DH) vs[threadIdx.x] = g_v[threadIdx.x];
    __syncthreads();
    int w    = (blockIdx.x * blockDim.x + threadIdx.x) >> 5;
    int lane = threadIdx.x & 31;
    if (w >= 2 * NN) return;
    uint4 u = *(const uint4*)(g_h16 + (size_t)w * DH + lane * 8);
    float4 v0 = ((const float4*)vs)[lane * 2];
    float4 v1 = ((const float4*)vs)[lane * 2 + 1];
    float2 f0 = __half22float2(*(const __half2*)&u.x);
    float2 f1 = __half22float2(*(const __half2*)&u.y);
    float2 f2 = __half22float2(*(const __half2*)&u.z);
    float2 f3 = __half22float2(*(const __half2*)&u.w);
    float acc = f0.x * v0.x + f0.y * v0.y + f1.x * v0.z + f1.y * v0.w
              + f2.x * v1.x + f2.y * v1.y + f3.x * v1.z + f3.y * v1.w;
#pragma unroll
    for (int o = 16; o > 0; o >>= 1) acc += __shfl_xor_sync(0xffffffffu, acc, o);
    if (lane == 0) out[w] = acc;
}

// ================= launch =================
extern "C" void kernel_launch(void* const* d_in, const int* in_sizes, int n_in,
                              void* d_out, int out_size) {
    const float* x       = (const float*)d_in[0];
    const float* x_tilde = (const float*)d_in[1];
    const float* vals    = (const float*)d_in[2];
    const int*   adj_row = (const int*)d_in[3];
    const int*   adj_col = (const int*)d_in[4];
    const float* W1      = (const float*)d_in[5];
    const float* prelu_a = (const float*)d_in[6];
    const float* w_bil   = (const float*)d_in[7];
    float* out = (float*)d_out;

    cudaFuncSetAttribute(k_gemm_mma, cudaFuncAttributeMaxDynamicSharedMemorySize, SM_BYTES);

    k_init<<<1, 256>>>();
    k_cvtW<<<(DH * DIN + 255) / 256, 256>>>(W1);
    k_rowptr<<<(EE + 255) / 256, 256>>>(adj_row);
    k_cvt<<<(NN * 32 + 255) / 256, 256>>>((const float4*)x, (const float4*)x_tilde);
    k_spmm<<<(NN * 32) / 256, 256>>>(vals, adj_col);
    int tiles = (2 * NN + 127) / 128;
    k_gemm_mma<<<tiles, 512, SM_BYTES>>>(prelu_a);
    k_sv<<<1, DH>>>(w_bil);
    k_dot<<<(2 * NN * 32 + 255) / 256, 256>>>(out);
}

// round 5
// speedup vs baseline: 2.4012x; 1.1601x over previous
#include <cuda_runtime.h>
#include <cuda_fp16.h>
#include <math.h>
#include <stdint.h>

#define NN 100000
#define EE 1600000
#define DIN 128
#define DH  256

// ---- device scratch (allocation-free contract) ----
__device__ uint4  g_xh[(size_t)NN * 32];        // interleaved fp16 x|x_tilde [N][256]h (51.2MB)
__device__ __half g_agg16[2ull * NN * DIN];     // fp16 agg (51.2MB)
__device__ __half g_W1h[DH * DIN];              // fp16 W1 [256][128] K-major
__device__ float  g_colsum[DH];
__device__ float  g_v[DH];
__device__ int    g_rowptr[NN + 1];

// ================= helpers =================
__device__ __forceinline__ uint32_t smem_u32(const void* p) {
    uint32_t a;
    asm("{ .reg .u64 t; cvta.to.shared.u64 t, %1; cvt.u32.u64 %0, t; }" : "=r"(a) : "l"(p));
    return a;
}
__device__ __forceinline__ void ldsm_x4(uint32_t& r0, uint32_t& r1, uint32_t& r2, uint32_t& r3,
                                        uint32_t addr) {
    asm volatile("ldmatrix.sync.aligned.m8n8.x4.shared.b16 {%0,%1,%2,%3}, [%4];"
                 : "=r"(r0), "=r"(r1), "=r"(r2), "=r"(r3) : "r"(addr));
}
__device__ __forceinline__ void mma16816(float* d, const uint32_t* a, const uint32_t* b) {
    asm volatile("mma.sync.aligned.m16n8k16.row.col.f32.f16.f16.f32 "
                 "{%0,%1,%2,%3}, {%4,%5,%6,%7}, {%8,%9}, {%0,%1,%2,%3};"
                 : "+f"(d[0]), "+f"(d[1]), "+f"(d[2]), "+f"(d[3])
                 : "r"(a[0]), "r"(a[1]), "r"(a[2]), "r"(a[3]), "r"(b[0]), "r"(b[1]));
}

// ================= fused prep: cvt | rowptr | cvtW+init =================
#define CVT_BLOCKS 12500
#define ROW_BLOCKS 6250
__global__ void k_prep(const float4* __restrict__ x4, const float4* __restrict__ xt4,
                       const int* __restrict__ adj_row, const float* __restrict__ W1) {
    int b = blockIdx.x, t = threadIdx.x;
    if (b < CVT_BLOCKS) {
        int i = b * 256 + t;
        if (i >= NN * 32) return;
        int row = i >> 5, j = i & 31;
        const float4* src = (j < 16) ? x4 : xt4;
        int jj = j & 15;
        float4 a = src[(size_t)row * 32 + jj * 2];
        float4 c = src[(size_t)row * 32 + jj * 2 + 1];
        __half2 h0 = __floats2half2_rn(a.x, a.y);
        __half2 h1 = __floats2half2_rn(a.z, a.w);
        __half2 h2 = __floats2half2_rn(c.x, c.y);
        __half2 h3 = __floats2half2_rn(c.z, c.w);
        uint4 o;
        o.x = *(unsigned*)&h0; o.y = *(unsigned*)&h1;
        o.z = *(unsigned*)&h2; o.w = *(unsigned*)&h3;
        g_xh[(size_t)row * 32 + j] = o;
    } else if (b < CVT_BLOCKS + ROW_BLOCKS) {
        int e = (b - CVT_BLOCKS) * 256 + t;
        if (e >= EE) return;
        int r  = adj_row[e];
        int rp = (e == 0) ? -1 : adj_row[e - 1];
        for (int k = rp + 1; k <= r; k++) g_rowptr[k] = e;
        if (e == EE - 1)
            for (int k = r + 1; k <= NN; k++) g_rowptr[k] = EE;
    } else {
        int wb = b - CVT_BLOCKS - ROW_BLOCKS;
        int i = wb * 256 + t;
        if (i < DH * DIN) g_W1h[i] = __float2half_rn(W1[i]);
        if (wb == 0) g_colsum[t] = 0.0f;
    }
}

// ================= SpMM (fp16 gather, fp16 agg out) =================
__global__ void k_spmm(const float* __restrict__ vals, const int* __restrict__ cols) {
    int w    = (blockIdx.x * blockDim.x + threadIdx.x) >> 5;
    int lane = threadIdx.x & 31;
    if (w >= NN) return;
    int e0 = g_rowptr[w], e1 = g_rowptr[w + 1];
    float a0 = 0.f, a1 = 0.f, a2 = 0.f, a3 = 0.f, a4 = 0.f, a5 = 0.f, a6 = 0.f, a7 = 0.f;
#pragma unroll 4
    for (int e = e0; e < e1; e++) {
        float wt = __ldg(vals + e);
        int   c  = __ldg(cols + e);
        uint4 u  = g_xh[(size_t)c * 32 + lane];
        float2 f0 = __half22float2(*(const __half2*)&u.x);
        float2 f1 = __half22float2(*(const __half2*)&u.y);
        float2 f2 = __half22float2(*(const __half2*)&u.z);
        float2 f3 = __half22float2(*(const __half2*)&u.w);
        a0 += wt * f0.x; a1 += wt * f0.y;
        a2 += wt * f1.x; a3 += wt * f1.y;
        a4 += wt * f2.x; a5 += wt * f2.y;
        a6 += wt * f3.x; a7 += wt * f3.y;
    }
    size_t base = (lane < 16) ? (size_t)w : (size_t)NN + w;
    int j = lane & 15;
    __half2 h0 = __floats2half2_rn(a0, a1);
    __half2 h1 = __floats2half2_rn(a2, a3);
    __half2 h2 = __floats2half2_rn(a4, a5);
    __half2 h3 = __floats2half2_rn(a6, a7);
    uint4 o;
    o.x = *(unsigned*)&h0; o.y = *(unsigned*)&h1;
    o.z = *(unsigned*)&h2; o.w = *(unsigned*)&h3;
    ((uint4*)g_agg16)[base * 16 + j] = o;
}

// ================= HMMA GEMM (two passes, no h materialization) =================
// CTA tile 128x256, K=128 resident. 512 thr = 16 warps (2x8), warp tile 64x32.
// PASS1: rows<NN, PReLU -> colsum (atomics). PASS2: all rows, dot with v -> out.
#define LDA 136
#define LDB 136
#define SM_BYTES (128 * LDA * 2 + 256 * LDB * 2)   // 104448

template <int PASS>
__global__ void __launch_bounds__(512, 1) k_gemm_fused(const float* __restrict__ prelu_a,
                                                       float* __restrict__ out) {
    extern __shared__ __half smem[];
    __half* As = smem;               // [128][LDA]
    __half* Bs = smem + 128 * LDA;   // [256][LDB]
    int tid = threadIdx.x, lane = tid & 31, wid = tid >> 5;
    int warp_m = wid >> 3, warp_n = wid & 7;       // 2 x 8
    long rowBase = (long)blockIdx.x * 128;
    const long totalRows = 2L * NN;

    // ---- load A tile (zero-fill OOB rows) ----
    {
        const uint4* asrc = (const uint4*)g_agg16;
#pragma unroll
        for (int i = 0; i < 4; i++) {
            int c = tid + i * 512;
            int row = c >> 4, k4 = c & 15;
            long grow = rowBase + row;
            uint4 v = make_uint4(0u, 0u, 0u, 0u);
            if (grow < totalRows) v = asrc[(size_t)grow * 16 + k4];
            *(uint4*)(As + row * LDA + k4 * 8) = v;
        }
    }
    // ---- load B tile (all of W1h) ----
    {
        const uint4* bsrc = (const uint4*)g_W1h;
#pragma unroll
        for (int i = 0; i < 8; i++) {
            int c = tid + i * 512;
            int row = c >> 4, k4 = c & 15;
            *(uint4*)(Bs + row * LDB + k4 * 8) = bsrc[row * 16 + k4];
        }
    }
    __syncthreads();

    float acc[4][4][4];
#pragma unroll
    for (int mt = 0; mt < 4; mt++)
#pragma unroll
        for (int nt = 0; nt < 4; nt++)
#pragma unroll
            for (int q = 0; q < 4; q++) acc[mt][nt][q] = 0.f;

    int aRow = warp_m * 64 + (lane & 15);
    int aCol = (lane >> 4) * 8;
    int bGrp = lane >> 3;
    int bRowOff = ((bGrp >> 1) * 8) + (lane & 7);
    int bKadd = (bGrp & 1) * 8;

#pragma unroll
    for (int ks = 0; ks < 8; ks++) {
        uint32_t a[4][4];
#pragma unroll
        for (int mt = 0; mt < 4; mt++) {
            uint32_t addr = smem_u32(As + (aRow + mt * 16) * LDA + ks * 16 + aCol);
            ldsm_x4(a[mt][0], a[mt][1], a[mt][2], a[mt][3], addr);
        }
        uint32_t b[4][2];
#pragma unroll
        for (int np = 0; np < 2; np++) {
            uint32_t addr = smem_u32(Bs + (warp_n * 32 + np * 16 + bRowOff) * LDB + ks * 16 + bKadd);
            uint32_t r0, r1, r2, r3;
            ldsm_x4(r0, r1, r2, r3, addr);
            b[np * 2][0] = r0; b[np * 2][1] = r1;
            b[np * 2 + 1][0] = r2; b[np * 2 + 1][1] = r3;
        }
#pragma unroll
        for (int mt = 0; mt < 4; mt++)
#pragma unroll
            for (int nt = 0; nt < 4; nt++)
                mma16816(acc[mt][nt], a[mt], b[nt]);
    }

    float pa = prelu_a[0];
    int r4 = lane >> 2, c4 = (lane & 3) * 2;

    if (PASS == 1) {
        // ---- colsum of PReLU(z) for rows < NN ----
        float csum[8];
#pragma unroll
        for (int q = 0; q < 8; q++) csum[q] = 0.f;
#pragma unroll
        for (int mt = 0; mt < 4; mt++) {
            long r_lo = rowBase + warp_m * 64 + mt * 16 + r4;
            bool p_lo = r_lo < NN, p_hi = (r_lo + 8) < NN;
#pragma unroll
            for (int nt = 0; nt < 4; nt++) {
                float* d = acc[mt][nt];
                float z0 = (d[0] >= 0.f) ? d[0] : pa * d[0];
                float z1 = (d[1] >= 0.f) ? d[1] : pa * d[1];
                float z2 = (d[2] >= 0.f) ? d[2] : pa * d[2];
                float z3 = (d[3] >= 0.f) ? d[3] : pa * d[3];
                if (p_lo) { csum[nt * 2] += z0; csum[nt * 2 + 1] += z1; }
                if (p_hi) { csum[nt * 2] += z2; csum[nt * 2 + 1] += z3; }
            }
        }
#pragma unroll
        for (int o = 4; o <= 16; o <<= 1)
#pragma unroll
            for (int q = 0; q < 8; q++)
                csum[q] += __shfl_xor_sync(0xffffffffu, csum[q], o);
        if (lane < 4) {
#pragma unroll
            for (int q = 0; q < 8; q++)
                atomicAdd(&g_colsum[warp_n * 32 + (q >> 1) * 8 + lane * 2 + (q & 1)], csum[q]);
        }
    } else {
        // ---- out[row] = PReLU(z)[row,:] . v ----
        float vc[8];
#pragma unroll
        for (int q = 0; q < 8; q++)
            vc[q] = __ldg(&g_v[warp_n * 32 + (q >> 1) * 8 + c4 + (q & 1)]);
        float rsum[8];   // [mt][lo/hi]
#pragma unroll
        for (int mt = 0; mt < 4; mt++) {
            float slo = 0.f, shi = 0.f;
#pragma unroll
            for (int nt = 0; nt < 4; nt++) {
                float* d = acc[mt][nt];
                float z0 = (d[0] >= 0.f) ? d[0] : pa * d[0];
                float z1 = (d[1] >= 0.f) ? d[1] : pa * d[1];
                float z2 = (d[2] >= 0.f) ? d[2] : pa * d[2];
                float z3 = (d[3] >= 0.f) ? d[3] : pa * d[3];
                slo += z0 * vc[nt * 2] + z1 * vc[nt * 2 + 1];
                shi += z2 * vc[nt * 2] + z3 * vc[nt * 2 + 1];
            }
            rsum[mt * 2] = slo; rsum[mt * 2 + 1] = shi;
        }
#pragma unroll
        for (int o = 1; o <= 2; o <<= 1)
#pragma unroll
            for (int q = 0; q < 8; q++)
                rsum[q] += __shfl_xor_sync(0xffffffffu, rsum[q], o);

        __syncthreads();                 // done with As/Bs
        float* ostg = (float*)smem;      // [128]
        if (tid < 128) ostg[tid] = 0.f;
        __syncthreads();
        if ((lane & 3) == 0) {
#pragma unroll
            for (int mt = 0; mt < 4; mt++) {
                int rl = warp_m * 64 + mt * 16 + r4;
                atomicAdd(&ostg[rl],     rsum[mt * 2]);
                atomicAdd(&ostg[rl + 8], rsum[mt * 2 + 1]);
            }
        }
        __syncthreads();
        if (tid < 128) {
            long grow = rowBase + tid;
            if (grow < totalRows) out[grow] = ostg[tid];
        }
    }
}

// ================= readout =================
__global__ void k_sv(const float* __restrict__ w_bil) {
    __shared__ float s[DH];
    int t = threadIdx.x;
    float m = g_colsum[t] / (float)NN;
    s[t] = 1.f / (1.f + expf(-m));
    __syncthreads();
    float acc = 0.f;
#pragma unroll 8
    for (int j = 0; j < DH; j++) acc += w_bil[t * DH + j] * s[j];
    g_v[t] = acc;
}

// ================= launch =================
extern "C" void kernel_launch(void* const* d_in, const int* in_sizes, int n_in,
                              void* d_out, int out_size) {
    const float* x       = (const float*)d_in[0];
    const float* x_tilde = (const float*)d_in[1];
    const float* vals    = (const float*)d_in[2];
    const int*   adj_row = (const int*)d_in[3];
    const int*   adj_col = (const int*)d_in[4];
    const float* W1      = (const float*)d_in[5];
    const float* prelu_a = (const float*)d_in[6];
    const float* w_bil   = (const float*)d_in[7];
    float* out = (float*)d_out;

    cudaFuncSetAttribute(k_gemm_fused<1>, cudaFuncAttributeMaxDynamicSharedMemorySize, SM_BYTES);
    cudaFuncSetAttribute(k_gemm_fused<2>, cudaFuncAttributeMaxDynamicSharedMemorySize, SM_BYTES);

    int wblocks = (DH * DIN + 255) / 256;
    k_prep<<<CVT_BLOCKS + ROW_BLOCKS + wblocks, 256>>>(
        (const float4*)x, (const float4*)x_tilde, adj_row, W1);
    k_spmm<<<(NN * 32) / 256, 256>>>(vals, adj_col);
    int tiles1 = (NN + 127) / 128;
    k_gemm_fused<1><<<tiles1, 512, SM_BYTES>>>(prelu_a, out);
    k_sv<<<1, DH>>>(w_bil);
    int tiles2 = (2 * NN + 127) / 128;
    k_gemm_fused<2><<<tiles2, 512, SM_BYTES>>>(prelu_a, out);
}

// round 6
// speedup vs baseline: 3.0334x; 1.2633x over previous
#include <cuda_runtime.h>
#include <cuda_fp16.h>
#include <math.h>
#include <stdint.h>

#define NN 100000
#define EE 1600000
#define DIN 128
#define DH  256

// ---- device scratch (allocation-free contract) ----
__device__ uint4  g_xh[(size_t)NN * 32];        // interleaved fp16 x|x_tilde [N][256]h (51.2MB)
__device__ __half g_agg16[2ull * NN * DIN];     // fp16 agg (51.2MB)
__device__ __half g_W1h[DH * DIN];              // fp16 W1 [256][128] K-major
__device__ float  g_colsum[DH];
__device__ float  g_v[DH];
__device__ int    g_rowptr[NN + 1];

// ================= helpers =================
__device__ __forceinline__ uint32_t smem_u32(const void* p) {
    uint32_t a;
    asm("{ .reg .u64 t; cvta.to.shared.u64 t, %1; cvt.u32.u64 %0, t; }" : "=r"(a) : "l"(p));
    return a;
}
__device__ __forceinline__ void ldsm_x4(uint32_t& r0, uint32_t& r1, uint32_t& r2, uint32_t& r3,
                                        uint32_t addr) {
    asm volatile("ldmatrix.sync.aligned.m8n8.x4.shared.b16 {%0,%1,%2,%3}, [%4];"
                 : "=r"(r0), "=r"(r1), "=r"(r2), "=r"(r3) : "r"(addr));
}
__device__ __forceinline__ void mma16816(float* d, const uint32_t* a, const uint32_t* b) {
    asm volatile("mma.sync.aligned.m16n8k16.row.col.f32.f16.f16.f32 "
                 "{%0,%1,%2,%3}, {%4,%5,%6,%7}, {%8,%9}, {%0,%1,%2,%3};"
                 : "+f"(d[0]), "+f"(d[1]), "+f"(d[2]), "+f"(d[3])
                 : "r"(a[0]), "r"(a[1]), "r"(a[2]), "r"(a[3]), "r"(b[0]), "r"(b[1]));
}
__device__ __forceinline__ void cp_async16(uint32_t saddr, const void* gptr, int src_bytes) {
    uint64_t ga;
    asm("cvta.to.global.u64 %0, %1;" : "=l"(ga) : "l"(gptr));
    asm volatile("cp.async.cg.shared.global [%0], [%1], 16, %2;"
                 :: "r"(saddr), "l"(ga), "r"(src_bytes));
}
__device__ __forceinline__ void cp_commit() {
    asm volatile("cp.async.commit_group;");
}

// ================= fused prep: cvt | rowptr | cvtW+init =================
#define CVT_BLOCKS 12500
#define ROW_BLOCKS 6250
__global__ void k_prep(const float4* __restrict__ x4, const float4* __restrict__ xt4,
                       const int* __restrict__ adj_row, const float* __restrict__ W1) {
    int b = blockIdx.x, t = threadIdx.x;
    if (b < CVT_BLOCKS) {
        int i = b * 256 + t;
        if (i >= NN * 32) return;
        int row = i >> 5, j = i & 31;
        const float4* src = (j < 16) ? x4 : xt4;
        int jj = j & 15;
        float4 a = src[(size_t)row * 32 + jj * 2];
        float4 c = src[(size_t)row * 32 + jj * 2 + 1];
        __half2 h0 = __floats2half2_rn(a.x, a.y);
        __half2 h1 = __floats2half2_rn(a.z, a.w);
        __half2 h2 = __floats2half2_rn(c.x, c.y);
        __half2 h3 = __floats2half2_rn(c.z, c.w);
        uint4 o;
        o.x = *(unsigned*)&h0; o.y = *(unsigned*)&h1;
        o.z = *(unsigned*)&h2; o.w = *(unsigned*)&h3;
        g_xh[(size_t)row * 32 + j] = o;
    } else if (b < CVT_BLOCKS + ROW_BLOCKS) {
        int e = (b - CVT_BLOCKS) * 256 + t;
        if (e >= EE) return;
        int r  = adj_row[e];
        int rp = (e == 0) ? -1 : adj_row[e - 1];
        for (int k = rp + 1; k <= r; k++) g_rowptr[k] = e;
        if (e == EE - 1)
            for (int k = r + 1; k <= NN; k++) g_rowptr[k] = EE;
    } else {
        int wb = b - CVT_BLOCKS - ROW_BLOCKS;
        int i = wb * 256 + t;
        if (i < DH * DIN) g_W1h[i] = __float2half_rn(W1[i]);
        if (wb == 0) g_colsum[t] = 0.0f;
    }
}

// ================= SpMM (fp16 gather, fp16 agg out) =================
__global__ void k_spmm(const float* __restrict__ vals, const int* __restrict__ cols) {
    int w    = (blockIdx.x * blockDim.x + threadIdx.x) >> 5;
    int lane = threadIdx.x & 31;
    if (w >= NN) return;
    int e0 = g_rowptr[w], e1 = g_rowptr[w + 1];
    float a0 = 0.f, a1 = 0.f, a2 = 0.f, a3 = 0.f, a4 = 0.f, a5 = 0.f, a6 = 0.f, a7 = 0.f;
#pragma unroll 4
    for (int e = e0; e < e1; e++) {
        float wt = __ldg(vals + e);
        int   c  = __ldg(cols + e);
        uint4 u  = g_xh[(size_t)c * 32 + lane];
        float2 f0 = __half22float2(*(const __half2*)&u.x);
        float2 f1 = __half22float2(*(const __half2*)&u.y);
        float2 f2 = __half22float2(*(const __half2*)&u.z);
        float2 f3 = __half22float2(*(const __half2*)&u.w);
        a0 += wt * f0.x; a1 += wt * f0.y;
        a2 += wt * f1.x; a3 += wt * f1.y;
        a4 += wt * f2.x; a5 += wt * f2.y;
        a6 += wt * f3.x; a7 += wt * f3.y;
    }
    size_t base = (lane < 16) ? (size_t)w : (size_t)NN + w;
    int j = lane & 15;
    __half2 h0 = __floats2half2_rn(a0, a1);
    __half2 h1 = __floats2half2_rn(a2, a3);
    __half2 h2 = __floats2half2_rn(a4, a5);
    __half2 h3 = __floats2half2_rn(a6, a7);
    uint4 o;
    o.x = *(unsigned*)&h0; o.y = *(unsigned*)&h1;
    o.z = *(unsigned*)&h2; o.w = *(unsigned*)&h3;
    ((uint4*)g_agg16)[base * 16 + j] = o;
}

// ================= persistent HMMA GEMM (double-buffered A via cp.async) =================
// CTA tile 128x256, K=128 resident. 512 thr = 16 warps (2x8), warp tile 64x32.
// PASS1: rows<NN -> colsum (regs across tiles, one atomic flush).
// PASS2: all 2N rows -> out[row] = PReLU(z) . v.
#define LDA 136
#define LDB 136
#define ASZ (128 * LDA)                 // halves per A buffer
#define SM_HALVES (2 * ASZ + 256 * LDB)
#define SM_BYTES (SM_HALVES * 2 + 512)  // + ostg
#define GRID_GEMM 148

template <int PASS>
__global__ void __launch_bounds__(512, 1) k_gemm_fused(const float* __restrict__ prelu_a,
                                                       float* __restrict__ out) {
    extern __shared__ __half smem[];
    __half* Ab[2] = { smem, smem + ASZ };
    __half* Bs = smem + 2 * ASZ;                 // [256][LDB]
    float* ostg = (float*)(smem + SM_HALVES);    // [128]
    int tid = threadIdx.x, lane = tid & 31, wid = tid >> 5;
    int warp_m = wid >> 3, warp_n = wid & 7;     // 2 x 8
    const long totalRows = 2L * NN;
    const long ntiles = (PASS == 1) ? (NN + 127) / 128 : (2 * NN + 127) / 128;

    // ---- load B tile (all of W1h) once ----
    {
        const uint4* bsrc = (const uint4*)g_W1h;
#pragma unroll
        for (int i = 0; i < 8; i++) {
            int c = tid + i * 512;
            int row = c >> 4, k4 = c & 15;
            *(uint4*)(Bs + row * LDB + k4 * 8) = bsrc[row * 16 + k4];
        }
    }

    // ---- A prefetch helper (cp.async, zero-fill OOB via src_bytes=0) ----
    auto prefetchA = [&](long tile, __half* dst) {
        const uint4* asrc = (const uint4*)g_agg16;
        long rb = tile * 128;
#pragma unroll
        for (int i = 0; i < 4; i++) {
            int c = tid + i * 512;
            int row = c >> 4, k4 = c & 15;
            long grow = rb + row;
            int ok = (grow < totalRows) ? 16 : 0;
            long src = ok ? grow : 0;
            cp_async16(smem_u32(dst + row * LDA + k4 * 8), asrc + src * 16 + k4, ok);
        }
        cp_commit();
    };

    float pa = prelu_a[0];
    int r4 = lane >> 2, c4 = (lane & 3) * 2;
    int aRow = warp_m * 64 + (lane & 15);
    int aCol = (lane >> 4) * 8;
    int bGrp = lane >> 3;
    int bRowOff = ((bGrp >> 1) * 8) + (lane & 7);
    int bKadd = (bGrp & 1) * 8;

    float csum[8];
    if (PASS == 1) {
#pragma unroll
        for (int q = 0; q < 8; q++) csum[q] = 0.f;
    }
    float vc[8];
    if (PASS == 2) {
#pragma unroll
        for (int q = 0; q < 8; q++)
            vc[q] = __ldg(&g_v[warp_n * 32 + (q >> 1) * 8 + c4 + (q & 1)]);
    }

    int p = 0;
    long tile = blockIdx.x;
    if (tile < ntiles) prefetchA(tile, Ab[0]);

    for (; tile < ntiles; tile += GRID_GEMM) {
        long next = tile + GRID_GEMM;
        if (next < ntiles) {
            prefetchA(next, Ab[p ^ 1]);
            asm volatile("cp.async.wait_group 1;");
        } else {
            asm volatile("cp.async.wait_group 0;");
        }
        __syncthreads();

        __half* As = Ab[p];
        float acc[4][4][4];
#pragma unroll
        for (int mt = 0; mt < 4; mt++)
#pragma unroll
            for (int nt = 0; nt < 4; nt++)
#pragma unroll
                for (int q = 0; q < 4; q++) acc[mt][nt][q] = 0.f;

#pragma unroll
        for (int ks = 0; ks < 8; ks++) {
            uint32_t a[4][4];
#pragma unroll
            for (int mt = 0; mt < 4; mt++) {
                uint32_t addr = smem_u32(As + (aRow + mt * 16) * LDA + ks * 16 + aCol);
                ldsm_x4(a[mt][0], a[mt][1], a[mt][2], a[mt][3], addr);
            }
            uint32_t b[4][2];
#pragma unroll
            for (int np = 0; np < 2; np++) {
                uint32_t addr = smem_u32(Bs + (warp_n * 32 + np * 16 + bRowOff) * LDB + ks * 16 + bKadd);
                uint32_t r0, r1, r2, r3;
                ldsm_x4(r0, r1, r2, r3, addr);
                b[np * 2][0] = r0; b[np * 2][1] = r1;
                b[np * 2 + 1][0] = r2; b[np * 2 + 1][1] = r3;
            }
#pragma unroll
            for (int mt = 0; mt < 4; mt++)
#pragma unroll
                for (int nt = 0; nt < 4; nt++)
                    mma16816(acc[mt][nt], a[mt], b[nt]);
        }

        long rowBase = tile * 128;
        if (PASS == 1) {
#pragma unroll
            for (int mt = 0; mt < 4; mt++) {
                long r_lo = rowBase + warp_m * 64 + mt * 16 + r4;
                bool p_lo = r_lo < NN, p_hi = (r_lo + 8) < NN;
#pragma unroll
                for (int nt = 0; nt < 4; nt++) {
                    float* d = acc[mt][nt];
                    float z0 = (d[0] >= 0.f) ? d[0] : pa * d[0];
                    float z1 = (d[1] >= 0.f) ? d[1] : pa * d[1];
                    float z2 = (d[2] >= 0.f) ? d[2] : pa * d[2];
                    float z3 = (d[3] >= 0.f) ? d[3] : pa * d[3];
                    if (p_lo) { csum[nt * 2] += z0; csum[nt * 2 + 1] += z1; }
                    if (p_hi) { csum[nt * 2] += z2; csum[nt * 2 + 1] += z3; }
                }
            }
            __syncthreads();   // before next prefetch overwrites Ab[p]
        } else {
            float rsum[8];
#pragma unroll
            for (int mt = 0; mt < 4; mt++) {
                float slo = 0.f, shi = 0.f;
#pragma unroll
                for (int nt = 0; nt < 4; nt++) {
                    float* d = acc[mt][nt];
                    float z0 = (d[0] >= 0.f) ? d[0] : pa * d[0];
                    float z1 = (d[1] >= 0.f) ? d[1] : pa * d[1];
                    float z2 = (d[2] >= 0.f) ? d[2] : pa * d[2];
                    float z3 = (d[3] >= 0.f) ? d[3] : pa * d[3];
                    slo += z0 * vc[nt * 2] + z1 * vc[nt * 2 + 1];
                    shi += z2 * vc[nt * 2] + z3 * vc[nt * 2 + 1];
                }
                rsum[mt * 2] = slo; rsum[mt * 2 + 1] = shi;
            }
#pragma unroll
            for (int o = 1; o <= 2; o <<= 1)
#pragma unroll
                for (int q = 0; q < 8; q++)
                    rsum[q] += __shfl_xor_sync(0xffffffffu, rsum[q], o);

            if (tid < 128) ostg[tid] = 0.f;
            __syncthreads();
            if ((lane & 3) == 0) {
#pragma unroll
                for (int mt = 0; mt < 4; mt++) {
                    int rl = warp_m * 64 + mt * 16 + r4;
                    atomicAdd(&ostg[rl],     rsum[mt * 2]);
                    atomicAdd(&ostg[rl + 8], rsum[mt * 2 + 1]);
                }
            }
            __syncthreads();
            if (tid < 128) {
                long grow = rowBase + tid;
                if (grow < totalRows) out[grow] = ostg[tid];
            }
            __syncthreads();   // before next prefetch overwrites Ab[p]
        }
        p ^= 1;
    }

    if (PASS == 1) {
#pragma unroll
        for (int o = 4; o <= 16; o <<= 1)
#pragma unroll
            for (int q = 0; q < 8; q++)
                csum[q] += __shfl_xor_sync(0xffffffffu, csum[q], o);
        if (lane < 4) {
#pragma unroll
            for (int q = 0; q < 8; q++)
                atomicAdd(&g_colsum[warp_n * 32 + (q >> 1) * 8 + lane * 2 + (q & 1)], csum[q]);
        }
    }
}

// ================= readout: s = sigmoid(colsum/N), v[j] = w_bil[j,:].s =================
__global__ void k_sv(const float* __restrict__ w_bil) {
    __shared__ float s[DH];
    __shared__ float red[8];
    int t = threadIdx.x;
    float m = g_colsum[t] / (float)NN;
    s[t] = 1.f / (1.f + expf(-m));
    __syncthreads();
    int j = blockIdx.x;
    float pv = w_bil[j * DH + t] * s[t];
#pragma unroll
    for (int o = 16; o > 0; o >>= 1) pv += __shfl_xor_sync(0xffffffffu, pv, o);
    if ((t & 31) == 0) red[t >> 5] = pv;
    __syncthreads();
    if (t == 0) {
        float acc = 0.f;
#pragma unroll
        for (int u = 0; u < 8; u++) acc += red[u];
        g_v[j] = acc;
    }
}

// ================= launch =================
extern "C" void kernel_launch(void* const* d_in, const int* in_sizes, int n_in,
                              void* d_out, int out_size) {
    const float* x       = (const float*)d_in[0];
    const float* x_tilde = (const float*)d_in[1];
    const float* vals    = (const float*)d_in[2];
    const int*   adj_row = (const int*)d_in[3];
    const int*   adj_col = (const int*)d_in[4];
    const float* W1      = (const float*)d_in[5];
    const float* prelu_a = (const float*)d_in[6];
    const float* w_bil   = (const float*)d_in[7];
    float* out = (float*)d_out;

    cudaFuncSetAttribute(k_gemm_fused<1>, cudaFuncAttributeMaxDynamicSharedMemorySize, SM_BYTES);
    cudaFuncSetAttribute(k_gemm_fused<2>, cudaFuncAttributeMaxDynamicSharedMemorySize, SM_BYTES);

    int wblocks = (DH * DIN + 255) / 256;
    k_prep<<<CVT_BLOCKS + ROW_BLOCKS + wblocks, 256>>>(
        (const float4*)x, (const float4*)x_tilde, adj_row, W1);
    k_spmm<<<(NN * 32) / 256, 256>>>(vals, adj_col);
    k_gemm_fused<1><<<GRID_GEMM, 512, SM_BYTES>>>(prelu_a, out);
    k_sv<<<DH, DH>>>(w_bil);
    k_gemm_fused<2><<<GRID_GEMM, 512, SM_BYTES>>>(prelu_a, out);
}

// round 7
// speedup vs baseline: 3.1407x; 1.0354x over previous
#include <cuda_runtime.h>
#include <cuda_fp16.h>
#include <math.h>
#include <stdint.h>

#define NN 100000
#define EE 1600000
#define DIN 128
#define DH  256

// ---- device scratch (allocation-free contract) ----
__device__ uint4  g_xh[(size_t)NN * 32];        // interleaved fp16 x|x_tilde [N][256]h (51.2MB)
__device__ __half g_agg16[2ull * NN * DIN];     // fp16 agg (51.2MB)
__device__ __half g_W1h[DH * DIN];              // fp16 W1 [256][128] K-major
__device__ float  g_colsum[DH];
__device__ int    g_rowptr[NN + 1];
__device__ int    g_bar;

// ================= helpers =================
__device__ __forceinline__ uint32_t smem_u32(const void* p) {
    uint32_t a;
    asm("{ .reg .u64 t; cvta.to.shared.u64 t, %1; cvt.u32.u64 %0, t; }" : "=r"(a) : "l"(p));
    return a;
}
__device__ __forceinline__ void ldsm_x4(uint32_t& r0, uint32_t& r1, uint32_t& r2, uint32_t& r3,
                                        uint32_t addr) {
    asm volatile("ldmatrix.sync.aligned.m8n8.x4.shared.b16 {%0,%1,%2,%3}, [%4];"
                 : "=r"(r0), "=r"(r1), "=r"(r2), "=r"(r3) : "r"(addr));
}
__device__ __forceinline__ void mma16816(float* d, const uint32_t* a, const uint32_t* b) {
    asm volatile("mma.sync.aligned.m16n8k16.row.col.f32.f16.f16.f32 "
                 "{%0,%1,%2,%3}, {%4,%5,%6,%7}, {%8,%9}, {%0,%1,%2,%3};"
                 : "+f"(d[0]), "+f"(d[1]), "+f"(d[2]), "+f"(d[3])
                 : "r"(a[0]), "r"(a[1]), "r"(a[2]), "r"(a[3]), "r"(b[0]), "r"(b[1]));
}
__device__ __forceinline__ void mma16816h(uint32_t* d, const uint32_t* a, const uint32_t* b) {
    asm volatile("mma.sync.aligned.m16n8k16.row.col.f16.f16.f16.f16 "
                 "{%0,%1}, {%2,%3,%4,%5}, {%6,%7}, {%0,%1};"
                 : "+r"(d[0]), "+r"(d[1])
                 : "r"(a[0]), "r"(a[1]), "r"(a[2]), "r"(a[3]), "r"(b[0]), "r"(b[1]));
}
__device__ __forceinline__ uint32_t prelu2(uint32_t z, __half2 pa2) {
    __half2 h = *(__half2*)&z;
    __half2 zero = __half2half2(__ushort_as_half(0));
    __half2 r = __hfma2(__hmin2(h, zero), pa2, __hmax2(h, zero));
    return *(uint32_t*)&r;
}
__device__ __forceinline__ void cp_async16(uint32_t saddr, const void* gptr, int src_bytes) {
    uint64_t ga;
    asm("cvta.to.global.u64 %0, %1;" : "=l"(ga) : "l"(gptr));
    asm volatile("cp.async.cg.shared.global [%0], [%1], 16, %2;"
                 :: "r"(saddr), "l"(ga), "r"(src_bytes));
}
__device__ __forceinline__ void cp_commit() {
    asm volatile("cp.async.commit_group;");
}

// ================= fused prep: cvt | rowptr | cvtW+init =================
#define CVT_BLOCKS 12500
#define ROW_BLOCKS 6250
__global__ void k_prep(const float4* __restrict__ x4, const float4* __restrict__ xt4,
                       const int* __restrict__ adj_row, const float* __restrict__ W1) {
    int b = blockIdx.x, t = threadIdx.x;
    if (b < CVT_BLOCKS) {
        int i = b * 256 + t;
        if (i >= NN * 32) return;
        int row = i >> 5, j = i & 31;
        const float4* src = (j < 16) ? x4 : xt4;
        int jj = j & 15;
        float4 a = src[(size_t)row * 32 + jj * 2];
        float4 c = src[(size_t)row * 32 + jj * 2 + 1];
        __half2 h0 = __floats2half2_rn(a.x, a.y);
        __half2 h1 = __floats2half2_rn(a.z, a.w);
        __half2 h2 = __floats2half2_rn(c.x, c.y);
        __half2 h3 = __floats2half2_rn(c.z, c.w);
        uint4 o;
        o.x = *(unsigned*)&h0; o.y = *(unsigned*)&h1;
        o.z = *(unsigned*)&h2; o.w = *(unsigned*)&h3;
        g_xh[(size_t)row * 32 + j] = o;
    } else if (b < CVT_BLOCKS + ROW_BLOCKS) {
        int e = (b - CVT_BLOCKS) * 256 + t;
        if (e >= EE) return;
        int r  = adj_row[e];
        int rp = (e == 0) ? -1 : adj_row[e - 1];
        for (int k = rp + 1; k <= r; k++) g_rowptr[k] = e;
        if (e == EE - 1)
            for (int k = r + 1; k <= NN; k++) g_rowptr[k] = EE;
    } else {
        int wb = b - CVT_BLOCKS - ROW_BLOCKS;
        int i = wb * 256 + t;
        if (i < DH * DIN) g_W1h[i] = __float2half_rn(W1[i]);
        if (wb == 0) {
            g_colsum[t] = 0.0f;
            if (t == 0) g_bar = 0;
        }
    }
}

// ================= SpMM (fp16 gather, fp16 agg out) =================
__global__ void k_spmm(const float* __restrict__ vals, const int* __restrict__ cols) {
    int w    = (blockIdx.x * blockDim.x + threadIdx.x) >> 5;
    int lane = threadIdx.x & 31;
    if (w >= NN) return;
    int e0 = g_rowptr[w], e1 = g_rowptr[w + 1];
    float a0 = 0.f, a1 = 0.f, a2 = 0.f, a3 = 0.f, a4 = 0.f, a5 = 0.f, a6 = 0.f, a7 = 0.f;
#pragma unroll 4
    for (int e = e0; e < e1; e++) {
        float wt = __ldg(vals + e);
        int   c  = __ldg(cols + e);
        uint4 u  = g_xh[(size_t)c * 32 + lane];
        float2 f0 = __half22float2(*(const __half2*)&u.x);
        float2 f1 = __half22float2(*(const __half2*)&u.y);
        float2 f2 = __half22float2(*(const __half2*)&u.z);
        float2 f3 = __half22float2(*(const __half2*)&u.w);
        a0 += wt * f0.x; a1 += wt * f0.y;
        a2 += wt * f1.x; a3 += wt * f1.y;
        a4 += wt * f2.x; a5 += wt * f2.y;
        a6 += wt * f3.x; a7 += wt * f3.y;
    }
    size_t base = (lane < 16) ? (size_t)w : (size_t)NN + w;
    int j = lane & 15;
    __half2 h0 = __floats2half2_rn(a0, a1);
    __half2 h1 = __floats2half2_rn(a2, a3);
    __half2 h2 = __floats2half2_rn(a4, a5);
    __half2 h3 = __floats2half2_rn(a6, a7);
    uint4 o;
    o.x = *(unsigned*)&h0; o.y = *(unsigned*)&h1;
    o.z = *(unsigned*)&h2; o.w = *(unsigned*)&h3;
    ((uint4*)g_agg16)[base * 16 + j] = o;
}

// ================= single persistent GEMM kernel =================
// PASS1 (fp16 acc): rows<NN -> colsum.  Grid barrier.  s,v per CTA.
// PASS2 (fp32 acc): all 2N rows -> out[row] = PReLU(z) . v
#define LDA 136
#define LDB 136
#define ASZ (128 * LDA)
#define SM_HALVES (2 * ASZ + 256 * LDB)
#define SM_BYTES (SM_HALVES * 2 + 512 + 2048)
#define GRID_GEMM 148

__global__ void __launch_bounds__(512, 1) k_gemm_all(const float* __restrict__ prelu_a,
                                                     const float* __restrict__ w_bil,
                                                     float* __restrict__ out) {
    extern __shared__ __half smem[];
    __half* Ab[2] = { smem, smem + ASZ };
    __half* Bs = smem + 2 * ASZ;                  // [256][LDB]
    float* ostg = (float*)(smem + SM_HALVES);     // [128]
    float* sv   = ostg + 128;                     // s[256] then v[256]
    int tid = threadIdx.x, lane = tid & 31, wid = tid >> 5;
    int warp_m = wid >> 3, warp_n = wid & 7;      // 2 x 8
    const long totalRows = 2L * NN;

    // ---- load B (all of W1h) once ----
    {
        const uint4* bsrc = (const uint4*)g_W1h;
#pragma unroll
        for (int i = 0; i < 8; i++) {
            int c = tid + i * 512;
            int row = c >> 4, k4 = c & 15;
            *(uint4*)(Bs + row * LDB + k4 * 8) = bsrc[row * 16 + k4];
        }
    }

    auto prefetchA = [&](long tile, __half* dst) {
        const uint4* asrc = (const uint4*)g_agg16;
        long rb = tile * 128;
#pragma unroll
        for (int i = 0; i < 4; i++) {
            int c = tid + i * 512;
            int row = c >> 4, k4 = c & 15;
            long grow = rb + row;
            int ok = (grow < totalRows) ? 16 : 0;
            long src = ok ? grow : 0;
            cp_async16(smem_u32(dst + row * LDA + k4 * 8), asrc + src * 16 + k4, ok);
        }
        cp_commit();
    };

    float pa = prelu_a[0];
    __half2 pa2 = __float2half2_rn(pa);
    int r4 = lane >> 2, c4 = (lane & 3) * 2;
    int aRow = warp_m * 64 + (lane & 15);
    int aCol = (lane >> 4) * 8;
    int bGrp = lane >> 3;
    int bRowOff = ((bGrp >> 1) * 8) + (lane & 7);
    int bKadd = (bGrp & 1) * 8;

    // ================== PASS 1: colsum (fp16 acc) ==================
    {
        const long nt1 = (NN + 127) / 128;
        uint32_t csum2[4] = {0u, 0u, 0u, 0u};
        int p = 0;
        long tile = blockIdx.x;
        if (tile < nt1) prefetchA(tile, Ab[0]);
        for (; tile < nt1; tile += GRID_GEMM) {
            long next = tile + GRID_GEMM;
            if (next < nt1) {
                prefetchA(next, Ab[p ^ 1]);
                asm volatile("cp.async.wait_group 1;");
            } else {
                asm volatile("cp.async.wait_group 0;");
            }
            __syncthreads();

            __half* As = Ab[p];
            uint32_t acc[4][4][2];
#pragma unroll
            for (int mt = 0; mt < 4; mt++)
#pragma unroll
                for (int nt = 0; nt < 4; nt++) { acc[mt][nt][0] = 0u; acc[mt][nt][1] = 0u; }

#pragma unroll
            for (int ks = 0; ks < 8; ks++) {
                uint32_t a[4][4];
#pragma unroll
                for (int mt = 0; mt < 4; mt++) {
                    uint32_t addr = smem_u32(As + (aRow + mt * 16) * LDA + ks * 16 + aCol);
                    ldsm_x4(a[mt][0], a[mt][1], a[mt][2], a[mt][3], addr);
                }
                uint32_t b[4][2];
#pragma unroll
                for (int np = 0; np < 2; np++) {
                    uint32_t addr = smem_u32(Bs + (warp_n * 32 + np * 16 + bRowOff) * LDB + ks * 16 + bKadd);
                    uint32_t r0, r1, r2, r3;
                    ldsm_x4(r0, r1, r2, r3, addr);
                    b[np * 2][0] = r0; b[np * 2][1] = r1;
                    b[np * 2 + 1][0] = r2; b[np * 2 + 1][1] = r3;
                }
#pragma unroll
                for (int mt = 0; mt < 4; mt++)
#pragma unroll
                    for (int nt = 0; nt < 4; nt++)
                        mma16816h(acc[mt][nt], a[mt], b[nt]);
            }

            long rowBase = tile * 128;
#pragma unroll
            for (int mt = 0; mt < 4; mt++) {
                long r_lo = rowBase + warp_m * 64 + mt * 16 + r4;
                bool p_lo = r_lo < NN, p_hi = (r_lo + 8) < NN;
#pragma unroll
                for (int nt = 0; nt < 4; nt++) {
                    uint32_t z0 = prelu2(acc[mt][nt][0], pa2);
                    uint32_t z1 = prelu2(acc[mt][nt][1], pa2);
                    __half2 c = *(__half2*)&csum2[nt];
                    if (p_lo) c = __hadd2(c, *(__half2*)&z0);
                    if (p_hi) c = __hadd2(c, *(__half2*)&z1);
                    csum2[nt] = *(uint32_t*)&c;
                }
            }
            __syncthreads();
            p ^= 1;
        }
        // quad-row reduce then flush
#pragma unroll
        for (int o = 4; o <= 16; o <<= 1)
#pragma unroll
            for (int nt = 0; nt < 4; nt++) {
                uint32_t other = __shfl_xor_sync(0xffffffffu, csum2[nt], o);
                __half2 c = __hadd2(*(__half2*)&csum2[nt], *(__half2*)&other);
                csum2[nt] = *(uint32_t*)&c;
            }
        if (lane < 4) {
#pragma unroll
            for (int nt = 0; nt < 4; nt++) {
                float2 f = __half22float2(*(__half2*)&csum2[nt]);
                atomicAdd(&g_colsum[warp_n * 32 + nt * 8 + lane * 2],     f.x);
                atomicAdd(&g_colsum[warp_n * 32 + nt * 8 + lane * 2 + 1], f.y);
            }
        }
    }

    // ================== grid-wide barrier ==================
    __threadfence();
    __syncthreads();
    if (tid == 0) {
        atomicAdd(&g_bar, 1);
        while (*(volatile int*)&g_bar < GRID_GEMM) { }
    }
    __syncthreads();
    __threadfence();

    // ================== s = sigmoid(colsum/N), v = w_bil @ s ==================
    {
        const long nt2 = (2 * NN + 127) / 128;
        if (blockIdx.x < nt2) prefetchA(blockIdx.x, Ab[0]);   // overlap with v compute
        if (tid < 256) {
            float m = g_colsum[tid] / (float)NN;
            sv[tid] = 1.f / (1.f + expf(-m));
        }
        __syncthreads();
        int j0 = wid * 16;
#pragma unroll 2
        for (int jj = 0; jj < 16; jj++) {
            int j = j0 + jj;
            float a = 0.f;
#pragma unroll
            for (int u = 0; u < 8; u++)
                a += __ldg(&w_bil[j * DH + lane + u * 32]) * sv[lane + u * 32];
#pragma unroll
            for (int o = 16; o > 0; o >>= 1) a += __shfl_xor_sync(0xffffffffu, a, o);
            if (lane == 0) sv[DH + j] = a;
        }
        __syncthreads();
    }
    float* v = sv + DH;
    float vc[8];
#pragma unroll
    for (int q = 0; q < 8; q++)
        vc[q] = v[warp_n * 32 + (q >> 1) * 8 + c4 + (q & 1)];

    // ================== PASS 2: out = PReLU(z) . v (fp32 acc) ==================
    {
        const long nt2 = (2 * NN + 127) / 128;
        int p = 0;
        long tile = blockIdx.x;
        for (; tile < nt2; tile += GRID_GEMM) {
            long next = tile + GRID_GEMM;
            if (next < nt2) {
                prefetchA(next, Ab[p ^ 1]);
                asm volatile("cp.async.wait_group 1;");
            } else {
                asm volatile("cp.async.wait_group 0;");
            }
            __syncthreads();

            __half* As = Ab[p];
            float acc[4][4][4];
#pragma unroll
            for (int mt = 0; mt < 4; mt++)
#pragma unroll
                for (int nt = 0; nt < 4; nt++)
#pragma unroll
                    for (int q = 0; q < 4; q++) acc[mt][nt][q] = 0.f;

#pragma unroll
            for (int ks = 0; ks < 8; ks++) {
                uint32_t a[4][4];
#pragma unroll
                for (int mt = 0; mt < 4; mt++) {
                    uint32_t addr = smem_u32(As + (aRow + mt * 16) * LDA + ks * 16 + aCol);
                    ldsm_x4(a[mt][0], a[mt][1], a[mt][2], a[mt][3], addr);
                }
                uint32_t b[4][2];
#pragma unroll
                for (int np = 0; np < 2; np++) {
                    uint32_t addr = smem_u32(Bs + (warp_n * 32 + np * 16 + bRowOff) * LDB + ks * 16 + bKadd);
                    uint32_t r0, r1, r2, r3;
                    ldsm_x4(r0, r1, r2, r3, addr);
                    b[np * 2][0] = r0; b[np * 2][1] = r1;
                    b[np * 2 + 1][0] = r2; b[np * 2 + 1][1] = r3;
                }
#pragma unroll
                for (int mt = 0; mt < 4; mt++)
#pragma unroll
                    for (int nt = 0; nt < 4; nt++)
                        mma16816(acc[mt][nt], a[mt], b[nt]);
            }

            long rowBase = tile * 128;
            float rsum[8];
#pragma unroll
            for (int mt = 0; mt < 4; mt++) {
                float slo = 0.f, shi = 0.f;
#pragma unroll
                for (int nt = 0; nt < 4; nt++) {
                    float* d = acc[mt][nt];
                    float z0 = (d[0] >= 0.f) ? d[0] : pa * d[0];
                    float z1 = (d[1] >= 0.f) ? d[1] : pa * d[1];
                    float z2 = (d[2] >= 0.f) ? d[2] : pa * d[2];
                    float z3 = (d[3] >= 0.f) ? d[3] : pa * d[3];
                    slo += z0 * vc[nt * 2] + z1 * vc[nt * 2 + 1];
                    shi += z2 * vc[nt * 2] + z3 * vc[nt * 2 + 1];
                }
                rsum[mt * 2] = slo; rsum[mt * 2 + 1] = shi;
            }
#pragma unroll
            for (int o = 1; o <= 2; o <<= 1)
#pragma unroll
                for (int q = 0; q < 8; q++)
                    rsum[q] += __shfl_xor_sync(0xffffffffu, rsum[q], o);

            if (tid < 128) ostg[tid] = 0.f;
            __syncthreads();
            if ((lane & 3) == 0) {
#pragma unroll
                for (int mt = 0; mt < 4; mt++) {
                    int rl = warp_m * 64 + mt * 16 + r4;
                    atomicAdd(&ostg[rl],     rsum[mt * 2]);
                    atomicAdd(&ostg[rl + 8], rsum[mt * 2 + 1]);
                }
            }
            __syncthreads();
            if (tid < 128) {
                long grow = rowBase + tid;
                if (grow < totalRows) out[grow] = ostg[tid];
            }
            __syncthreads();
            p ^= 1;
        }
    }
}

// ================= launch =================
extern "C" void kernel_launch(void* const* d_in, const int* in_sizes, int n_in,
                              void* d_out, int out_size) {
    const float* x       = (const float*)d_in[0];
    const float* x_tilde = (const float*)d_in[1];
    const float* vals    = (const float*)d_in[2];
    const int*   adj_row = (const int*)d_in[3];
    const int*   adj_col = (const int*)d_in[4];
    const float* W1      = (const float*)d_in[5];
    const float* prelu_a = (const float*)d_in[6];
    const float* w_bil   = (const float*)d_in[7];
    float* out = (float*)d_out;

    cudaFuncSetAttribute(k_gemm_all, cudaFuncAttributeMaxDynamicSharedMemorySize, SM_BYTES);

    int wblocks = (DH * DIN + 255) / 256;
    k_prep<<<CVT_BLOCKS + ROW_BLOCKS + wblocks, 256>>>(
        (const float4*)x, (const float4*)x_tilde, adj_row, W1);
    k_spmm<<<(NN * 32) / 256, 256>>>(vals, adj_col);
    k_gemm_all<<<GRID_GEMM, 512, SM_BYTES>>>(prelu_a, w_bil, out);
}